// round 9
// baseline (speedup 1.0000x reference)
#include <cuda_runtime.h>
#include <cstdint>

// Aggregation: out[n, g*32+wc, h, w] =
//   sum_{kh,kw} x_reflect[n, g*32+wc, h+kh-1, w+kw-1] * weight[n, wc, kh*3+kw, h, w]
//
// x (8,256,128,128) f32, weight (8,32,9,128,128) f32, out = x shape.
//
// R9: cp.async (LDGSTS) staging. Register-MLP is capped (~11 float4 dests at
// the 80-reg budget) and every register/warp reshape around R4 lost. cp.async
// completes into SMEM with no destination registers and no queue depth cap,
// so phase kh+1's 8 x-copies stay in flight through phase kh's entire FMA
// drain. Each thread copies and consumes ONLY its own 16B slots -> no
// __syncthreads, just cp.async.wait_group. Double-buffered (64KB/CTA,
// 3 CTAs/SM = same 24 warps as R4). Weights keep the register prefetch path.

namespace {
constexpr int N  = 8;
constexpr int C  = 256;
constexpr int H  = 128;
constexpr int W  = 128;
constexpr int WC = 32;
constexpr int G  = C / WC;   // 8
constexpr int HW = H * W;
constexpr int CS = WC * HW;  // channel-group stride (elements)
constexpr int SMEM_BYTES = 2 * G * 256 * 16;  // 65536
}

__device__ __forceinline__ void cp_async16(uint32_t saddr, const float* gptr) {
    asm volatile("cp.async.cg.shared.global [%0], [%1], 16;\n"
                 :: "r"(saddr), "l"(gptr));
}
__device__ __forceinline__ void cp_commit() {
    asm volatile("cp.async.commit_group;\n");
}
template <int Nw>
__device__ __forceinline__ void cp_wait() {
    asm volatile("cp.async.wait_group %0;\n" :: "n"(Nw));
}

__global__ __launch_bounds__(256, 3)
void agg_kernel(const float* __restrict__ x,
                const float* __restrict__ wt,
                float* __restrict__ out)
{
    extern __shared__ float4 sbuf[];   // [2][G][256] float4 slots
    const uint32_t sbase =
        (uint32_t)__cvta_generic_to_shared(sbuf) + threadIdx.x * 16u;

    const int tid = blockIdx.x * 256 + threadIdx.x;
    // Decode: w4 (32) fastest -> lane id == w4; then h (128), wc (32), n (8)
    const int w4 = tid & 31;
    const int h  = (tid >> 5) & 127;
    const int wc = (tid >> 12) & 31;
    const int n  = tid >> 17;
    const int w  = w4 << 2;

    // Reflect rows (PAD=1: only -1 and 128 occur)
    const int hr0 = (h == 0)     ? 1     : h - 1;
    const int hr2 = (h == H - 1) ? H - 2 : h + 1;
    const int rows[3] = { hr0, h, hr2 };

    const bool lane_lo = (w4 == 0);
    const bool lane_hi = (w4 == 31);

    const size_t x_n_base = (size_t)n * C * HW;
    const float* xbase = x + x_n_base + (size_t)wc * HW + w;

    const float4* wp = reinterpret_cast<const float4*>(
        wt + ((size_t)(n * WC + wc) * 9) * HW + (size_t)h * W + w);

    float4 acc[G];
    #pragma unroll
    for (int g = 0; g < G; g++)
        acc[g] = make_float4(0.f, 0.f, 0.f, 0.f);

    // ---- Prologue: async-issue phase 0's 8 x-row copies ----
    {
        const float* xr = xbase + rows[0] * W;
        #pragma unroll
        for (int g = 0; g < G; g++)
            cp_async16(sbase + (0 * G + g) * (256 * 16), xr + g * CS);
        cp_commit();
    }

    // kh=0 weights issued up front (registers)
    float4 wA = __ldcs(wp + 0 * (HW / 4));
    float4 wB = __ldcs(wp + 1 * (HW / 4));
    float4 wD = __ldcs(wp + 2 * (HW / 4));

    #pragma unroll
    for (int kh = 0; kh < 3; kh++) {
        const int cur = kh & 1;

        // ---- Async-issue next phase's 8 x copies (in flight across drain) ----
        if (kh < 2) {
            const float* xr = xbase + rows[kh + 1] * W;
            #pragma unroll
            for (int g = 0; g < G; g++)
                cp_async16(sbase + ((cur ^ 1) * G + g) * (256 * 16), xr + g * CS);
            cp_commit();
        }

        // prefetch next kh's weights (3 register loads in flight too)
        float4 nA, nB, nD;
        if (kh < 2) {
            nA = __ldcs(wp + ((kh + 1) * 3 + 0) * (HW / 4));
            nB = __ldcs(wp + ((kh + 1) * 3 + 1) * (HW / 4));
            nD = __ldcs(wp + ((kh + 1) * 3 + 2) * (HW / 4));
        }

        // wait for current phase only (leave next phase pending)
        if (kh < 2) cp_wait<1>(); else cp_wait<0>();

        #pragma unroll
        for (int g = 0; g < G; g++) {
            const float4 xm = sbuf[(cur * G + g) * 256 + threadIdx.x];
            const float v1 = xm.x, v2 = xm.y, v3 = xm.z, v4 = xm.w;
            // halo via warp shuffle; reflect at row ends is intra-lane
            float v0 = __shfl_up_sync(0xffffffffu, v4, 1);
            float v5 = __shfl_down_sync(0xffffffffu, v1, 1);
            if (lane_lo) v0 = v2;   // col -1  -> col 1
            if (lane_hi) v5 = v3;   // col 128 -> col 126

            acc[g].x = fmaf(v0, wA.x, fmaf(v1, wB.x, fmaf(v2, wD.x, acc[g].x)));
            acc[g].y = fmaf(v1, wA.y, fmaf(v2, wB.y, fmaf(v3, wD.y, acc[g].y)));
            acc[g].z = fmaf(v2, wA.z, fmaf(v3, wB.z, fmaf(v4, wD.z, acc[g].z)));
            acc[g].w = fmaf(v3, wA.w, fmaf(v4, wB.w, fmaf(v5, wD.w, acc[g].w)));
        }

        if (kh < 2) { wA = nA; wB = nB; wD = nD; }
    }

    // One contiguous write burst: 8 streaming float4 stores
    float* ob = out + x_n_base + (size_t)wc * HW + (size_t)h * W + w;
    #pragma unroll
    for (int g = 0; g < G; g++)
        __stcs(reinterpret_cast<float4*>(ob + g * CS), acc[g]);
}

extern "C" void kernel_launch(void* const* d_in, const int* in_sizes, int n_in,
                              void* d_out, int out_size)
{
    const float* x  = (const float*)d_in[0];
    const float* wt = (const float*)d_in[1];
    float* out      = (float*)d_out;

    cudaFuncSetAttribute(agg_kernel,
                         cudaFuncAttributeMaxDynamicSharedMemorySize,
                         SMEM_BYTES);

    const int total   = N * WC * H * (W / 4);  // 1,048,576 threads
    const int threads = 256;
    const int blocks  = total / threads;       // 4096
    agg_kernel<<<blocks, threads, SMEM_BYTES>>>(x, wt, out);
}

// round 10
// speedup vs baseline: 1.0306x; 1.0306x over previous
#include <cuda_runtime.h>

// Aggregation: out[n, g*32+wc, h, w] =
//   sum_{kh,kw} x_reflect[n, g*32+wc, h+kh-1, w+kw-1] * weight[n, wc, kh*3+kw, h, w]
//
// x (8,256,128,128) f32, weight (8,32,9,128,128) f32, out = x shape.
//
// R4 shape (best: 66.0us, DRAM 78%): one-shot 4096-CTA grid, kh-phase batches
// of 3 wt + 8 x float4 loads, 32 acc regs, 3 CTAs/SM (24 warps).
// R10 = R4 with the final kh phase peeled: each acc[g] is stored immediately
// after its last FMA, overlapping the store burst with the tail compute
// instead of serializing 8 stores behind the full FMA drain.
// R5-R9 lessons: warp count, batch depth, grid shape, load mechanism are all
// at their optimum — touch nothing else.

namespace {
constexpr int N  = 8;
constexpr int C  = 256;
constexpr int H  = 128;
constexpr int W  = 128;
constexpr int WC = 32;
constexpr int G  = C / WC;   // 8
constexpr int HW = H * W;
constexpr int CS = WC * HW;  // channel-group stride (elements)
}

__global__ __launch_bounds__(256, 3)
void agg_kernel(const float* __restrict__ x,
                const float* __restrict__ wt,
                float* __restrict__ out)
{
    const int tid = blockIdx.x * 256 + threadIdx.x;
    // Decode: w4 (32) fastest -> lane id == w4; then h (128), wc (32), n (8)
    const int w4 = tid & 31;
    const int h  = (tid >> 5) & 127;
    const int wc = (tid >> 12) & 31;
    const int n  = tid >> 17;
    const int w  = w4 << 2;

    // Reflect rows (PAD=1: only -1 and 128 occur)
    const int hr0 = (h == 0)     ? 1     : h - 1;
    const int hr2 = (h == H - 1) ? H - 2 : h + 1;
    const int rows[3] = { hr0, h, hr2 };

    const bool lane_lo = (w4 == 0);
    const bool lane_hi = (w4 == 31);

    const size_t x_n_base = (size_t)n * C * HW;
    const float* xbase = x + x_n_base + (size_t)wc * HW + w;
    float*       obase = out + x_n_base + (size_t)wc * HW + (size_t)h * W + w;

    const float4* wp = reinterpret_cast<const float4*>(
        wt + ((size_t)(n * WC + wc) * 9) * HW + (size_t)h * W + w);

    float4 acc[G];
    #pragma unroll
    for (int g = 0; g < G; g++)
        acc[g] = make_float4(0.f, 0.f, 0.f, 0.f);

    // ---- Phases kh = 0, 1: accumulate ----
    #pragma unroll
    for (int kh = 0; kh < 2; kh++) {
        const float4 wA = __ldcs(wp + (kh * 3 + 0) * (HW / 4));
        const float4 wB = __ldcs(wp + (kh * 3 + 1) * (HW / 4));
        const float4 wD = __ldcs(wp + (kh * 3 + 2) * (HW / 4));

        const float* xr = xbase + rows[kh] * W;
        float4 xm[G];
        #pragma unroll
        for (int g = 0; g < G; g++)
            xm[g] = *reinterpret_cast<const float4*>(xr + g * CS);

        #pragma unroll
        for (int g = 0; g < G; g++) {
            const float v1 = xm[g].x, v2 = xm[g].y,
                        v3 = xm[g].z, v4 = xm[g].w;
            float v0 = __shfl_up_sync(0xffffffffu, v4, 1);
            float v5 = __shfl_down_sync(0xffffffffu, v1, 1);
            if (lane_lo) v0 = v2;   // col -1  -> col 1
            if (lane_hi) v5 = v3;   // col 128 -> col 126

            acc[g].x = fmaf(v0, wA.x, fmaf(v1, wB.x, fmaf(v2, wD.x, acc[g].x)));
            acc[g].y = fmaf(v1, wA.y, fmaf(v2, wB.y, fmaf(v3, wD.y, acc[g].y)));
            acc[g].z = fmaf(v2, wA.z, fmaf(v3, wB.z, fmaf(v4, wD.z, acc[g].z)));
            acc[g].w = fmaf(v3, wA.w, fmaf(v4, wB.w, fmaf(v5, wD.w, acc[g].w)));
        }
    }

    // ---- Final phase kh = 2: accumulate and store each group immediately ----
    {
        const float4 wA = __ldcs(wp + 6 * (HW / 4));
        const float4 wB = __ldcs(wp + 7 * (HW / 4));
        const float4 wD = __ldcs(wp + 8 * (HW / 4));

        const float* xr = xbase + rows[2] * W;
        float4 xm[G];
        #pragma unroll
        for (int g = 0; g < G; g++)
            xm[g] = *reinterpret_cast<const float4*>(xr + g * CS);

        #pragma unroll
        for (int g = 0; g < G; g++) {
            const float v1 = xm[g].x, v2 = xm[g].y,
                        v3 = xm[g].z, v4 = xm[g].w;
            float v0 = __shfl_up_sync(0xffffffffu, v4, 1);
            float v5 = __shfl_down_sync(0xffffffffu, v1, 1);
            if (lane_lo) v0 = v2;
            if (lane_hi) v5 = v3;

            float4 o;
            o.x = fmaf(v0, wA.x, fmaf(v1, wB.x, fmaf(v2, wD.x, acc[g].x)));
            o.y = fmaf(v1, wA.y, fmaf(v2, wB.y, fmaf(v3, wD.y, acc[g].y)));
            o.z = fmaf(v2, wA.z, fmaf(v3, wB.z, fmaf(v4, wD.z, acc[g].z)));
            o.w = fmaf(v3, wA.w, fmaf(v4, wB.w, fmaf(v5, wD.w, acc[g].w)));

            // store as soon as this group's result is final
            __stcs(reinterpret_cast<float4*>(obase + g * CS), o);
        }
    }
}

extern "C" void kernel_launch(void* const* d_in, const int* in_sizes, int n_in,
                              void* d_out, int out_size)
{
    const float* x  = (const float*)d_in[0];
    const float* wt = (const float*)d_in[1];
    float* out      = (float*)d_out;

    const int total   = N * WC * H * (W / 4);  // 1,048,576 threads
    const int threads = 256;
    const int blocks  = total / threads;       // 4096
    agg_kernel<<<blocks, threads>>>(x, wt, out);
}

// round 11
// speedup vs baseline: 1.0579x; 1.0265x over previous
#include <cuda_runtime.h>

// Aggregation: out[n, g*32+wc, h, w] =
//   sum_{kh,kw} x_reflect[n, g*32+wc, h+kh-1, w+kw-1] * weight[n, wc, kh*3+kw, h, w]
//
// x (8,256,128,128) f32, weight (8,32,9,128,128) f32, out = x shape.
//
// FINAL (R4 config, best of 10 rounds: 66.0us, DRAM 78%, 6.19 TB/s):
// - DRAM traffic at the algorithmic floor (~390MB): weights register-resident
//   across all 8 channel groups, halo columns via warp shuffle (a warp spans
//   one full W=128 row), reflect edges intra-lane.
// - kh-outer phases: 3 weight + 8 independent x float4 loads batched
//   back-to-back (deep MLP), 32 persistent accumulator registers, all 8
//   output stores as one contiguous streaming burst at the end.
// - 3 CTAs/SM (80 regs, 24 warps). Verified optimum: more warps (R5), manual
//   double-buffering (R6), persistent grid (R7), weight prefetch (R8),
//   cp.async staging (R9), and store interleave (R10) all measured worse.

namespace {
constexpr int N  = 8;
constexpr int C  = 256;
constexpr int H  = 128;
constexpr int W  = 128;
constexpr int WC = 32;
constexpr int G  = C / WC;   // 8
constexpr int HW = H * W;
constexpr int CS = WC * HW;  // channel-group stride (elements)
}

__global__ __launch_bounds__(256, 3)
void agg_kernel(const float* __restrict__ x,
                const float* __restrict__ wt,
                float* __restrict__ out)
{
    const int tid = blockIdx.x * 256 + threadIdx.x;
    // Decode: w4 (32) fastest -> lane id == w4; then h (128), wc (32), n (8)
    const int w4 = tid & 31;
    const int h  = (tid >> 5) & 127;
    const int wc = (tid >> 12) & 31;
    const int n  = tid >> 17;
    const int w  = w4 << 2;

    // Reflect rows (PAD=1: only -1 and 128 occur)
    const int hr0 = (h == 0)     ? 1     : h - 1;
    const int hr2 = (h == H - 1) ? H - 2 : h + 1;
    const int rows[3] = { hr0, h, hr2 };

    const bool lane_lo = (w4 == 0);
    const bool lane_hi = (w4 == 31);

    const size_t x_n_base = (size_t)n * C * HW;
    const float* xbase = x + x_n_base + (size_t)wc * HW + w;

    const float4* wp = reinterpret_cast<const float4*>(
        wt + ((size_t)(n * WC + wc) * 9) * HW + (size_t)h * W + w);

    float4 acc[G];
    #pragma unroll
    for (int g = 0; g < G; g++)
        acc[g] = make_float4(0.f, 0.f, 0.f, 0.f);

    #pragma unroll
    for (int kh = 0; kh < 3; kh++) {
        // 3 weight float4s for this kh (read-once: evict-first)
        const float4 wA = __ldcs(wp + (kh * 3 + 0) * (HW / 4));
        const float4 wB = __ldcs(wp + (kh * 3 + 1) * (HW / 4));
        const float4 wD = __ldcs(wp + (kh * 3 + 2) * (HW / 4));

        // 8 independent x-row loads, batched back-to-back
        const float* xr = xbase + rows[kh] * W;
        float4 xm[G];
        #pragma unroll
        for (int g = 0; g < G; g++)
            xm[g] = *reinterpret_cast<const float4*>(xr + g * CS);

        #pragma unroll
        for (int g = 0; g < G; g++) {
            const float v1 = xm[g].x, v2 = xm[g].y,
                        v3 = xm[g].z, v4 = xm[g].w;
            // halo via warp shuffle; reflect at row ends is intra-lane
            float v0 = __shfl_up_sync(0xffffffffu, v4, 1);
            float v5 = __shfl_down_sync(0xffffffffu, v1, 1);
            if (lane_lo) v0 = v2;   // col -1  -> col 1
            if (lane_hi) v5 = v3;   // col 128 -> col 126

            acc[g].x = fmaf(v0, wA.x, fmaf(v1, wB.x, fmaf(v2, wD.x, acc[g].x)));
            acc[g].y = fmaf(v1, wA.y, fmaf(v2, wB.y, fmaf(v3, wD.y, acc[g].y)));
            acc[g].z = fmaf(v2, wA.z, fmaf(v3, wB.z, fmaf(v4, wD.z, acc[g].z)));
            acc[g].w = fmaf(v3, wA.w, fmaf(v4, wB.w, fmaf(v5, wD.w, acc[g].w)));
        }
    }

    // One contiguous write burst: 8 streaming float4 stores
    float* ob = out + x_n_base + (size_t)wc * HW + (size_t)h * W + w;
    #pragma unroll
    for (int g = 0; g < G; g++)
        __stcs(reinterpret_cast<float4*>(ob + g * CS), acc[g]);
}

extern "C" void kernel_launch(void* const* d_in, const int* in_sizes, int n_in,
                              void* d_out, int out_size)
{
    const float* x  = (const float*)d_in[0];
    const float* wt = (const float*)d_in[1];
    float* out      = (float*)d_out;

    const int total   = N * WC * H * (W / 4);  // 1,048,576 threads
    const int threads = 256;
    const int blocks  = total / threads;       // 4096
    agg_kernel<<<blocks, threads>>>(x, wt, out);
}